// round 5
// baseline (speedup 1.0000x reference)
#include <cuda_runtime.h>
#include <math.h>

#define NB 64
#define NT 512
#define NVARS 16
#define VDIM 16
#define DD 64
#define NTOK (NB*NT)
#define TPB 256
#define TOKCTA 256
#define SSP 257          // u64 row stride in S/R (bank-conflict-free)
#define LN_EPS 1e-3f

typedef unsigned long long u64;

// ---------------- packed f32x2 helpers ----------------
#define FMA2(d, a, b) asm("fma.rn.f32x2 %0, %1, %2, %0;" : "+l"(d) : "l"(a), "l"(b))
#define ADD2(d, a, b) asm("add.rn.f32x2 %0, %1, %2;" : "=l"(d) : "l"(a), "l"(b))
#define MUL2(d, a, b) asm("mul.rn.f32x2 %0, %1, %2;" : "=l"(d) : "l"(a), "l"(b))

__device__ __forceinline__ void unpack2(u64 v, float& a, float& b) {
    unsigned int x, y;
    asm("mov.b64 {%0,%1}, %2;" : "=r"(x), "=r"(y) : "l"(v));
    a = __uint_as_float(x); b = __uint_as_float(y);
}
__device__ __forceinline__ u64 pack2(float a, float b) {
    u64 v;
    asm("mov.b64 %0, {%1,%2};" : "=l"(v)
        : "r"(__float_as_uint(a)), "r"(__float_as_uint(b)));
    return v;
}
__device__ __forceinline__ u64 dup2(float a) {
    u64 v;
    asm("mov.b64 %0, {%1,%1};" : "=l"(v) : "r"(__float_as_uint(a)));
    return v;
}

__device__ __forceinline__ float eluf(float x) {
    return x > 0.f ? x : (__expf(x) - 1.f);
}
__device__ __forceinline__ float sigm(float x) {
    return __fdividef(1.f, 1.f + __expf(-x));
}

// smem float offsets
#define OFF_S      0                         // u64[32*257] = 65792 B
#define OFF_R      16448                     // u64[32*257]
#define OFF_W      32896                     // 272*64 floats = 69632 B
#define OFF_BIAS   (OFF_W + 272*DD)          // 7*64
#define OFF_CPROJ  (OFF_BIAS + 7*DD)         // 16*64
#define OFF_WSEL   (OFF_CPROJ + NVARS*DD)    // 256*16
#define OFF_CTX    (OFF_WSEL + TOKCTA*NVARS) // 64
#define SMEM_FLOATS (OFF_CTX + DD)

// acc[j*8+i]: token j (0..3), u64-dim-pair i (dims q*16+2i, q*16+2i+1)
template <int KP>
__device__ __forceinline__ void matvec4(const float* __restrict__ Wq,
                                        const u64* __restrict__ Sb,
                                        u64 acc[32]) {
#pragma unroll 4
    for (int kp = 0; kp < KP; ++kp) {
        u64 p0 = Sb[kp * SSP];
        u64 p1 = Sb[kp * SSP + 64];
        u64 p2 = Sb[kp * SSP + 128];
        u64 p3 = Sb[kp * SSP + 192];
        float x00, x01, x10, x11, x20, x21, x30, x31;
        unpack2(p0, x00, x01); unpack2(p1, x10, x11);
        unpack2(p2, x20, x21); unpack2(p3, x30, x31);
        u64 d00 = dup2(x00), d10 = dup2(x10), d20 = dup2(x20), d30 = dup2(x30);
        u64 d01 = dup2(x01), d11 = dup2(x11), d21 = dup2(x21), d31 = dup2(x31);
        const ulonglong2* w0 = (const ulonglong2*)(Wq + (2 * kp) * DD);
        const ulonglong2* w1 = (const ulonglong2*)(Wq + (2 * kp + 1) * DD);
#pragma unroll
        for (int m = 0; m < 4; ++m) {
            ulonglong2 wa = w0[m];
            FMA2(acc[0 * 8 + 2 * m], d00, wa.x); FMA2(acc[0 * 8 + 2 * m + 1], d00, wa.y);
            FMA2(acc[1 * 8 + 2 * m], d10, wa.x); FMA2(acc[1 * 8 + 2 * m + 1], d10, wa.y);
            FMA2(acc[2 * 8 + 2 * m], d20, wa.x); FMA2(acc[2 * 8 + 2 * m + 1], d20, wa.y);
            FMA2(acc[3 * 8 + 2 * m], d30, wa.x); FMA2(acc[3 * 8 + 2 * m + 1], d30, wa.y);
        }
#pragma unroll
        for (int m = 0; m < 4; ++m) {
            ulonglong2 wb = w1[m];
            FMA2(acc[0 * 8 + 2 * m], d01, wb.x); FMA2(acc[0 * 8 + 2 * m + 1], d01, wb.y);
            FMA2(acc[1 * 8 + 2 * m], d11, wb.x); FMA2(acc[1 * 8 + 2 * m + 1], d11, wb.y);
            FMA2(acc[2 * 8 + 2 * m], d21, wb.x); FMA2(acc[2 * 8 + 2 * m + 1], d21, wb.y);
            FMA2(acc[3 * 8 + 2 * m], d31, wb.x); FMA2(acc[3 * 8 + 2 * m + 1], d31, wb.y);
        }
    }
}

__device__ __forceinline__ void load_bias4(const float* __restrict__ bsm, int q,
                                           u64 acc[32]) {
    const u64* b = (const u64*)(bsm + q * 16);
#pragma unroll
    for (int i = 0; i < 8; i++) {
        u64 v = b[i];
        acc[0 * 8 + i] = v; acc[1 * 8 + i] = v;
        acc[2 * 8 + i] = v; acc[3 * 8 + i] = v;
    }
}

__device__ __forceinline__ void store_stage(u64* __restrict__ S, int col, int q,
                                            const u64 acc[32]) {
#pragma unroll
    for (int i = 0; i < 8; i++) {
        int r = (q * 8 + i) * SSP + col;
        S[r] = acc[0 * 8 + i];
        S[r + 64] = acc[1 * 8 + i];
        S[r + 128] = acc[2 * 8 + i];
        S[r + 192] = acc[3 * 8 + i];
    }
}

// ---------------------------------------------------------------------------
__global__ __launch_bounds__(TPB, 1) void vsn_fused_kernel(
    const float* __restrict__ inputs, const float* __restrict__ context,
    const float* __restrict__ Wt, const float* __restrict__ bt,
    const float* __restrict__ Wctx,
    const float* __restrict__ W1, const float* __restrict__ b1,
    const float* __restrict__ W2, const float* __restrict__ b2,
    const float* __restrict__ Wg, const float* __restrict__ bg,
    const float* __restrict__ Wp, const float* __restrict__ bp,
    const float* __restrict__ gamma_, const float* __restrict__ beta_,
    const float* __restrict__ Ws, const float* __restrict__ bs,
    float* __restrict__ selected, float* __restrict__ wout) {
    extern __shared__ __align__(16) float smem[];
    u64* S = (u64*)(smem + OFF_S);
    u64* R = (u64*)(smem + OFF_R);
    float* W_s = smem + OFF_W;
    float* bias_s = smem + OFF_BIAS;
    float* cproj_s = smem + OFF_CPROJ;
    float* wsel_s = smem + OFF_WSEL;
    float* ctx_s = smem + OFF_CTX;

    const int tid = threadIdx.x;
    const int slot = tid >> 2;     // 0..63 : token column
    const int q = tid & 3;         // dim quarter
    const int base = blockIdx.x * TOKCTA;
    const int b = base / NT;

    // ---------- phase 0: stage Ws/bs/ctx ----------
    {
        const float4* s = (const float4*)Ws;
        float4* d = (float4*)W_s;
        for (int i = tid; i < 1024; i += TPB) d[i] = s[i];
        if (tid < 16) bias_s[tid] = bs[tid];
        if (tid < DD) ctx_s[tid] = context[(size_t)b * DD + tid];
    }
    __syncthreads();

    // ---------- phase 1a: per-token softmax (1 token/thread) ----------
    {
        int token = base + tid;
        const float4* xp = (const float4*)(inputs + (size_t)token * 256);
        u64 lg[8];
#pragma unroll
        for (int j = 0; j < 8; j++) lg[j] = ((const u64*)bias_s)[j];
#pragma unroll 4
        for (int f4 = 0; f4 < 64; ++f4) {
            float4 xv = xp[f4];
            const float* wr = W_s + f4 * 64;
#pragma unroll
            for (int c = 0; c < 4; c++) {
                float x = (c == 0) ? xv.x : (c == 1) ? xv.y : (c == 2) ? xv.z : xv.w;
                u64 x2 = dup2(x);
                const u64* w2 = (const u64*)(wr + c * 16);
#pragma unroll
                for (int j = 0; j < 8; j++) FMA2(lg[j], x2, w2[j]);
            }
        }
        float l[16];
#pragma unroll
        for (int j = 0; j < 8; j++) unpack2(lg[j], l[2 * j], l[2 * j + 1]);
        float mx = l[0];
#pragma unroll
        for (int i = 1; i < 16; i++) mx = fmaxf(mx, l[i]);
        float sum = 0.f;
#pragma unroll
        for (int i = 0; i < 16; i++) { l[i] = __expf(l[i] - mx); sum += l[i]; }
        float inv = __fdividef(1.f, sum);
        float4* gp = (float4*)(wout + (size_t)token * 16);
        float4* sp = (float4*)(wsel_s + tid * 16);
#pragma unroll
        for (int j = 0; j < 4; j++) {
            float4 o;
            o.x = l[4 * j + 0] * inv; o.y = l[4 * j + 1] * inv;
            o.z = l[4 * j + 2] * inv; o.w = l[4 * j + 3] * inv;
            gp[j] = o;
            sp[j] = o;
        }
    }

    // ---------- phase 1b: cproj for this CTA's batch row ----------
    {
        int n = tid >> 4;
        int e = (tid & 15) * 4;
        const float* W = Wctx + (size_t)n * DD * DD;
        float4 acc = make_float4(0.f, 0.f, 0.f, 0.f);
#pragma unroll 8
        for (int d = 0; d < DD; ++d) {
            float c = ctx_s[d];
            float4 w = *(const float4*)(W + d * DD + e);
            acc.x = fmaf(c, w.x, acc.x); acc.y = fmaf(c, w.y, acc.y);
            acc.z = fmaf(c, w.z, acc.z); acc.w = fmaf(c, w.w, acc.w);
        }
        *(float4*)(cproj_s + n * DD + e) = acc;
    }

    u64 sel[32];
#pragma unroll
    for (int i = 0; i < 32; i++) sel[i] = 0ull;

    const u64* Sb = S + slot;      // activation base for matvec
    const int col = slot;

    // W_s rows: Wt [0,16), Wp [16,80), W1 [80,144), W2 [144,208), Wg [208,272)
    for (int n = 0; n < NVARS; ++n) {
        __syncthreads();
        // plain row-major weight staging (contiguous copies)
        {
            const float4* s0 = (const float4*)(Wt + (size_t)n * VDIM * DD);
            float4* d0 = (float4*)(W_s);
            for (int i = tid; i < 256; i += TPB) d0[i] = s0[i];
            const float4* s1 = (const float4*)(Wp + (size_t)n * DD * DD);
            float4* d1 = (float4*)(W_s + 16 * DD);
            for (int i = tid; i < 1024; i += TPB) d1[i] = s1[i];
            const float4* s2 = (const float4*)(W1 + (size_t)n * DD * DD);
            float4* d2 = (float4*)(W_s + 80 * DD);
            for (int i = tid; i < 1024; i += TPB) d2[i] = s2[i];
            const float4* s3 = (const float4*)(W2 + (size_t)n * DD * DD);
            float4* d3 = (float4*)(W_s + 144 * DD);
            for (int i = tid; i < 1024; i += TPB) d3[i] = s3[i];
            const float4* s4 = (const float4*)(Wg + (size_t)n * DD * DD);
            float4* d4 = (float4*)(W_s + 208 * DD);
            for (int i = tid; i < 1024; i += TPB) d4[i] = s4[i];
        }
        if (tid < DD) {
            bias_s[0 * DD + tid] = bt[n * DD + tid];
            bias_s[1 * DD + tid] = bp[n * DD + tid];
            bias_s[2 * DD + tid] = b1[n * DD + tid];
            bias_s[3 * DD + tid] = b2[n * DD + tid];
            bias_s[4 * DD + tid] = bg[n * DD + tid];
            bias_s[5 * DD + tid] = gamma_[n * DD + tid];
            bias_s[6 * DD + tid] = beta_[n * DD + tid];
        }
        __syncthreads();

        // stage x slices: thread q loads dims [q*4, q*4+4) of each of its tokens
#pragma unroll
        for (int j = 0; j < 4; j++) {
            int tok = base + slot + 64 * j;
            float4 v = *(const float4*)(inputs + (size_t)tok * 256 + n * VDIM + q * 4);
            S[(q * 2) * SSP + col + 64 * j] = pack2(v.x, v.y);
            S[(q * 2 + 1) * SSP + col + 64 * j] = pack2(v.z, v.w);
        }
        __syncwarp();

        const float* Wq_t = W_s + q * 16;
        const float* Wq_p = W_s + 16 * DD + q * 16;
        const float* Wq_1 = W_s + 80 * DD + q * 16;
        const float* Wq_2 = W_s + 144 * DD + q * 16;
        const float* Wq_g = W_s + 208 * DD + q * 16;

        u64 acc[32];
        // t = x @ Wt + bt
        load_bias4(bias_s + 0 * DD, q, acc);
        matvec4<8>(Wq_t, Sb, acc);
        __syncwarp();                     // x reads done
        store_stage(S, col, q, acc);      // S = t
        __syncwarp();
        // residual = t @ Wp + bp -> R
        load_bias4(bias_s + 1 * DD, q, acc);
        matvec4<32>(Wq_p, Sb, acc);
        store_stage(R, col, q, acc);
        __syncwarp();                     // t reads done
        // a = t + cproj (RMW own rows)
        {
            const u64* cp = (const u64*)(cproj_s + n * DD + q * 16);
#pragma unroll
            for (int i = 0; i < 8; i++) {
                int r = (q * 8 + i) * SSP + col;
                u64 c = cp[i];
                u64 v0 = S[r], v1 = S[r + 64], v2 = S[r + 128], v3 = S[r + 192];
                ADD2(v0, v0, c); ADD2(v1, v1, c); ADD2(v2, v2, c); ADD2(v3, v3, c);
                S[r] = v0; S[r + 64] = v1; S[r + 128] = v2; S[r + 192] = v3;
            }
        }
        __syncwarp();
        // h1 = elu(a @ W1 + b1)
        load_bias4(bias_s + 2 * DD, q, acc);
        matvec4<32>(Wq_1, Sb, acc);
#pragma unroll
        for (int i = 0; i < 32; i++) {
            float e0, e1;
            unpack2(acc[i], e0, e1);
            acc[i] = pack2(eluf(e0), eluf(e1));
        }
        __syncwarp();
        store_stage(S, col, q, acc);      // S = h1
        __syncwarp();
        // h2 = h1 @ W2 + b2
        load_bias4(bias_s + 3 * DD, q, acc);
        matvec4<32>(Wq_2, Sb, acc);
        __syncwarp();
        store_stage(S, col, q, acc);      // S = h2
        __syncwarp();
        // gate logits
        load_bias4(bias_s + 4 * DD, q, acc);
        matvec4<32>(Wq_g, Sb, acc);
        // y = residual + sigmoid(gate)*h2
#pragma unroll
        for (int j = 0; j < 4; j++) {
#pragma unroll
            for (int i = 0; i < 8; i++) {
                int r = (q * 8 + i) * SSP + col + 64 * j;
                float g0, g1;
                unpack2(acc[j * 8 + i], g0, g1);
                u64 gpk = pack2(sigm(g0), sigm(g1));
                u64 y = R[r];
                FMA2(y, gpk, S[r]);
                acc[j * 8 + i] = y;
            }
        }
        // LayerNorm (4-lane butterfly) + weighted select, per token
        const u64* g64 = (const u64*)(bias_s + 5 * DD + q * 16);
        const u64* be64 = (const u64*)(bias_s + 6 * DD + q * 16);
#pragma unroll
        for (int j = 0; j < 4; j++) {
            u64* a = acc + j * 8;
            u64 s2 = a[0];
#pragma unroll
            for (int i = 1; i < 8; i++) ADD2(s2, s2, a[i]);
            float sa, sb; unpack2(s2, sa, sb);
            float part = sa + sb;
            part += __shfl_xor_sync(0xffffffffu, part, 1);
            part += __shfl_xor_sync(0xffffffffu, part, 2);
            float mu = part * (1.f / 64.f);
            u64 negmu = dup2(-mu);
            u64 v2 = 0ull;
#pragma unroll
            for (int i = 0; i < 8; i++) {
                u64 d; ADD2(d, a[i], negmu); FMA2(v2, d, d);
            }
            float va, vb; unpack2(v2, va, vb);
            float vpart = va + vb;
            vpart += __shfl_xor_sync(0xffffffffu, vpart, 1);
            vpart += __shfl_xor_sync(0xffffffffu, vpart, 2);
            float var = vpart * (1.f / 64.f);
            u64 rs2 = dup2(rsqrtf(var + LN_EPS));
            u64 w2 = dup2(wsel_s[(slot + 64 * j) * NVARS + n]);
#pragma unroll
            for (int i = 0; i < 8; i++) {
                u64 d, t2, y;
                ADD2(d, a[i], negmu);
                MUL2(t2, d, rs2);
                y = be64[i];
                FMA2(y, t2, g64[i]);
                FMA2(sel[j * 8 + i], w2, y);
            }
        }
    }

    // output: 16 dims x 4 tokens
#pragma unroll
    for (int j = 0; j < 4; j++) {
        int tok = base + slot + 64 * j;
        ulonglong2* op = (ulonglong2*)(selected + (size_t)tok * DD + q * 16);
#pragma unroll
        for (int m = 0; m < 4; m++) {
            ulonglong2 o;
            o.x = sel[j * 8 + 2 * m];
            o.y = sel[j * 8 + 2 * m + 1];
            op[m] = o;
        }
    }
}

// ---------------------------------------------------------------------------
extern "C" void kernel_launch(void* const* d_in, const int* in_sizes, int n_in,
                              void* d_out, int out_size) {
    const float* inputs  = (const float*)d_in[0];
    const float* context = (const float*)d_in[1];
    const float* Wt   = (const float*)d_in[2];
    const float* bt   = (const float*)d_in[3];
    const float* Wctx = (const float*)d_in[4];
    const float* W1   = (const float*)d_in[5];
    const float* b1   = (const float*)d_in[6];
    const float* W2   = (const float*)d_in[7];
    const float* b2   = (const float*)d_in[8];
    const float* Wg   = (const float*)d_in[9];
    const float* bg   = (const float*)d_in[10];
    const float* Wp   = (const float*)d_in[11];
    const float* bp   = (const float*)d_in[12];
    const float* gam  = (const float*)d_in[13];
    const float* bet  = (const float*)d_in[14];
    const float* Ws   = (const float*)d_in[15];
    const float* bs   = (const float*)d_in[16];

    float* selected = (float*)d_out;
    float* wout = selected + (size_t)NTOK * DD;

    size_t smem_bytes = (size_t)SMEM_FLOATS * sizeof(float);
    cudaFuncSetAttribute(vsn_fused_kernel,
                         cudaFuncAttributeMaxDynamicSharedMemorySize,
                         (int)smem_bytes);
    vsn_fused_kernel<<<NTOK / TOKCTA, TPB, smem_bytes>>>(
        inputs, context, Wt, bt, Wctx, W1, b1, W2, b2, Wg, bg, Wp, bp,
        gam, bet, Ws, bs, selected, wout);
}

// round 6
// speedup vs baseline: 1.2286x; 1.2286x over previous
#include <cuda_runtime.h>
#include <math.h>

#define NB 64
#define NT 512
#define NVARS 16
#define VDIM 16
#define DD 64
#define NTOK (NB*NT)
#define TPB 256
#define TOKCTA 256
#define SSP 257          // u64 row stride in S/R
#define QS_BIG 1028      // quarter stride (floats) for 64x64 matrices
#define QS_WT  260       // quarter stride (floats) for Wt (16x64)
#define LN_EPS 1e-3f

typedef unsigned long long u64;

// ---------------- packed f32x2 helpers ----------------
#define FMA2(d, a, b) asm("fma.rn.f32x2 %0, %1, %2, %0;" : "+l"(d) : "l"(a), "l"(b))
#define ADD2(d, a, b) asm("add.rn.f32x2 %0, %1, %2;" : "=l"(d) : "l"(a), "l"(b))
#define MUL2(d, a, b) asm("mul.rn.f32x2 %0, %1, %2;" : "=l"(d) : "l"(a), "l"(b))

__device__ __forceinline__ void unpack2(u64 v, float& a, float& b) {
    unsigned int x, y;
    asm("mov.b64 {%0,%1}, %2;" : "=r"(x), "=r"(y) : "l"(v));
    a = __uint_as_float(x); b = __uint_as_float(y);
}
__device__ __forceinline__ u64 pack2(float a, float b) {
    u64 v;
    asm("mov.b64 %0, {%1,%2};" : "=l"(v)
        : "r"(__float_as_uint(a)), "r"(__float_as_uint(b)));
    return v;
}
__device__ __forceinline__ u64 dup2(float a) {
    u64 v;
    asm("mov.b64 %0, {%1,%1};" : "=l"(v) : "r"(__float_as_uint(a)));
    return v;
}

__device__ __forceinline__ float eluf(float x) {
    return x > 0.f ? x : (__expf(x) - 1.f);
}
__device__ __forceinline__ float sigm(float x) {
    return __fdividef(1.f, 1.f + __expf(-x));
}

// smem float offsets
#define OFF_S      0                         // u64[32*257]
#define OFF_R      16448
#define OFF_W      32896                     // 17488 floats quarter-major
#define OFF_BIAS   (OFF_W + 17488)           // 7*64
#define OFF_CPROJ  (OFF_BIAS + 7*DD)         // 16*64
#define OFF_WSEL   (OFF_CPROJ + NVARS*DD)    // 256*16
#define OFF_CTX    (OFF_WSEL + TOKCTA*NVARS) // 64
#define SMEM_FLOATS (OFF_CTX + DD)
// matrix bases within W_s (floats)
#define WB_T  0
#define WB_P  1040
#define WB_1  5152
#define WB_2  9264
#define WB_G  13376

// acc[j*8+i]: token j (0..3), u64-dim-pair i (dims q*16+2i, q*16+2i+1)
// Wq: quarter-major base for this thread's q (16 floats/row).
// Activation row permutation: true pair p -> row (p%8)*4 + p/8.
template <int KP>
__device__ __forceinline__ void matvec4(const float* __restrict__ Wq,
                                        const u64* __restrict__ Sb,
                                        u64 acc[32]) {
#pragma unroll 2
    for (int kp = 0; kp < KP; ++kp) {
        int arow = ((kp & 7) << 2) | (kp >> 3);
        u64 p0 = Sb[arow * SSP];
        u64 p1 = Sb[arow * SSP + 64];
        u64 p2 = Sb[arow * SSP + 128];
        u64 p3 = Sb[arow * SSP + 192];
        float x00, x01, x10, x11, x20, x21, x30, x31;
        unpack2(p0, x00, x01); unpack2(p1, x10, x11);
        unpack2(p2, x20, x21); unpack2(p3, x30, x31);
        u64 d00 = dup2(x00), d10 = dup2(x10), d20 = dup2(x20), d30 = dup2(x30);
        u64 d01 = dup2(x01), d11 = dup2(x11), d21 = dup2(x21), d31 = dup2(x31);
        const ulonglong2* w0 = (const ulonglong2*)(Wq + (2 * kp) * 16);
        const ulonglong2* w1 = (const ulonglong2*)(Wq + (2 * kp + 1) * 16);
#pragma unroll
        for (int m = 0; m < 4; ++m) {
            ulonglong2 wa = w0[m];
            FMA2(acc[0 * 8 + 2 * m], d00, wa.x); FMA2(acc[0 * 8 + 2 * m + 1], d00, wa.y);
            FMA2(acc[1 * 8 + 2 * m], d10, wa.x); FMA2(acc[1 * 8 + 2 * m + 1], d10, wa.y);
            FMA2(acc[2 * 8 + 2 * m], d20, wa.x); FMA2(acc[2 * 8 + 2 * m + 1], d20, wa.y);
            FMA2(acc[3 * 8 + 2 * m], d30, wa.x); FMA2(acc[3 * 8 + 2 * m + 1], d30, wa.y);
        }
#pragma unroll
        for (int m = 0; m < 4; ++m) {
            ulonglong2 wb = w1[m];
            FMA2(acc[0 * 8 + 2 * m], d01, wb.x); FMA2(acc[0 * 8 + 2 * m + 1], d01, wb.y);
            FMA2(acc[1 * 8 + 2 * m], d11, wb.x); FMA2(acc[1 * 8 + 2 * m + 1], d11, wb.y);
            FMA2(acc[2 * 8 + 2 * m], d21, wb.x); FMA2(acc[2 * 8 + 2 * m + 1], d21, wb.y);
            FMA2(acc[3 * 8 + 2 * m], d31, wb.x); FMA2(acc[3 * 8 + 2 * m + 1], d31, wb.y);
        }
    }
}

__device__ __forceinline__ void load_bias4(const float* __restrict__ bsm, int q,
                                           u64 acc[32]) {
    const u64* b = (const u64*)(bsm + q * 16);
#pragma unroll
    for (int i = 0; i < 8; i++) {
        u64 v = b[i];
        acc[0 * 8 + i] = v; acc[1 * 8 + i] = v;
        acc[2 * 8 + i] = v; acc[3 * 8 + i] = v;
    }
}

// thread (q) local pair i lives at row i*4+q
__device__ __forceinline__ void store_stage(u64* __restrict__ S, int col, int q,
                                            const u64 acc[32]) {
#pragma unroll
    for (int i = 0; i < 8; i++) {
        int r = (i * 4 + q) * SSP + col;
        S[r] = acc[0 * 8 + i];
        S[r + 64] = acc[1 * 8 + i];
        S[r + 128] = acc[2 * 8 + i];
        S[r + 192] = acc[3 * 8 + i];
    }
}

// ---------------------------------------------------------------------------
__global__ __launch_bounds__(TPB, 1) void vsn_fused_kernel(
    const float* __restrict__ inputs, const float* __restrict__ context,
    const float* __restrict__ Wt, const float* __restrict__ bt,
    const float* __restrict__ Wctx,
    const float* __restrict__ W1, const float* __restrict__ b1,
    const float* __restrict__ W2, const float* __restrict__ b2,
    const float* __restrict__ Wg, const float* __restrict__ bg,
    const float* __restrict__ Wp, const float* __restrict__ bp,
    const float* __restrict__ gamma_, const float* __restrict__ beta_,
    const float* __restrict__ Ws, const float* __restrict__ bs,
    float* __restrict__ selected, float* __restrict__ wout) {
    extern __shared__ __align__(16) float smem[];
    u64* S = (u64*)(smem + OFF_S);
    u64* R = (u64*)(smem + OFF_R);
    float* W_s = smem + OFF_W;
    float* bias_s = smem + OFF_BIAS;
    float* cproj_s = smem + OFF_CPROJ;
    float* wsel_s = smem + OFF_WSEL;
    float* ctx_s = smem + OFF_CTX;

    const int tid = threadIdx.x;
    const int slot = tid >> 2;     // 0..63 token column
    const int q = tid & 3;         // dim quarter
    const int base = blockIdx.x * TOKCTA;
    const int b = base / NT;

    // ---------- phase 0: stage Ws/bs/ctx ----------
    {
        const float4* s = (const float4*)Ws;
        float4* d = (float4*)W_s;
        for (int i = tid; i < 1024; i += TPB) d[i] = s[i];
        if (tid < 16) bias_s[tid] = bs[tid];
        if (tid < DD) ctx_s[tid] = context[(size_t)b * DD + tid];
    }
    __syncthreads();

    // ---------- phase 1a: per-token softmax (1 token/thread) ----------
    {
        int token = base + tid;
        const float4* xp = (const float4*)(inputs + (size_t)token * 256);
        u64 lg[8];
#pragma unroll
        for (int j = 0; j < 8; j++) lg[j] = ((const u64*)bias_s)[j];
#pragma unroll 4
        for (int f4 = 0; f4 < 64; ++f4) {
            float4 xv = xp[f4];
            const float* wr = W_s + f4 * 64;
#pragma unroll
            for (int c = 0; c < 4; c++) {
                float x = (c == 0) ? xv.x : (c == 1) ? xv.y : (c == 2) ? xv.z : xv.w;
                u64 x2 = dup2(x);
                const u64* w2 = (const u64*)(wr + c * 16);
#pragma unroll
                for (int j = 0; j < 8; j++) FMA2(lg[j], x2, w2[j]);
            }
        }
        float l[16];
#pragma unroll
        for (int j = 0; j < 8; j++) unpack2(lg[j], l[2 * j], l[2 * j + 1]);
        float mx = l[0];
#pragma unroll
        for (int i = 1; i < 16; i++) mx = fmaxf(mx, l[i]);
        float sum = 0.f;
#pragma unroll
        for (int i = 0; i < 16; i++) { l[i] = __expf(l[i] - mx); sum += l[i]; }
        float inv = __fdividef(1.f, sum);
        float4* gp = (float4*)(wout + (size_t)token * 16);
        float4* sp = (float4*)(wsel_s + tid * 16);
#pragma unroll
        for (int j = 0; j < 4; j++) {
            float4 o;
            o.x = l[4 * j + 0] * inv; o.y = l[4 * j + 1] * inv;
            o.z = l[4 * j + 2] * inv; o.w = l[4 * j + 3] * inv;
            gp[j] = o;
            sp[j] = o;
        }
    }

    // ---------- phase 1b: cproj for this CTA's batch row ----------
    {
        int n = tid >> 4;
        int e = (tid & 15) * 4;
        const float* W = Wctx + (size_t)n * DD * DD;
        float4 acc = make_float4(0.f, 0.f, 0.f, 0.f);
#pragma unroll 8
        for (int d = 0; d < DD; ++d) {
            float c = ctx_s[d];
            float4 w = *(const float4*)(W + d * DD + e);
            acc.x = fmaf(c, w.x, acc.x); acc.y = fmaf(c, w.y, acc.y);
            acc.z = fmaf(c, w.z, acc.z); acc.w = fmaf(c, w.w, acc.w);
        }
        *(float4*)(cproj_s + n * DD + e) = acc;
    }

    u64 sel[32];
#pragma unroll
    for (int i = 0; i < 32; i++) sel[i] = 0ull;

    const u64* Sb = S + slot;
    const int col = slot;

    for (int n = 0; n < NVARS; ++n) {
        __syncthreads();
        // quarter-major weight staging
        {
            const float4* s0 = (const float4*)(Wt + (size_t)n * VDIM * DD);
            float4* d0 = (float4*)(W_s + WB_T);
            for (int i = tid; i < 256; i += TPB) {
                int row = i >> 4, c = i & 15;
                d0[(c >> 2) * (QS_WT / 4) + row * 4 + (c & 3)] = s0[i];
            }
            const float* srcs[4] = {Wp + (size_t)n * DD * DD, W1 + (size_t)n * DD * DD,
                                    W2 + (size_t)n * DD * DD, Wg + (size_t)n * DD * DD};
            const int bases[4] = {WB_P, WB_1, WB_2, WB_G};
#pragma unroll
            for (int jm = 0; jm < 4; jm++) {
                const float4* sj = (const float4*)srcs[jm];
                float4* dj = (float4*)(W_s + bases[jm]);
                for (int i = tid; i < 1024; i += TPB) {
                    int row = i >> 4, c = i & 15;
                    dj[(c >> 2) * (QS_BIG / 4) + row * 4 + (c & 3)] = sj[i];
                }
            }
        }
        if (tid < DD) {
            bias_s[0 * DD + tid] = bt[n * DD + tid];
            bias_s[1 * DD + tid] = bp[n * DD + tid];
            bias_s[2 * DD + tid] = b1[n * DD + tid];
            bias_s[3 * DD + tid] = b2[n * DD + tid];
            bias_s[4 * DD + tid] = bg[n * DD + tid];
            bias_s[5 * DD + tid] = gamma_[n * DD + tid];
            bias_s[6 * DD + tid] = beta_[n * DD + tid];
        }
        __syncthreads();

        // stage x slices: thread q loads dims [q*4, q*4+4) (true pairs 2q, 2q+1
        // -> rows 8q, 8q+4 under perm) for each of its 4 tokens
#pragma unroll
        for (int j = 0; j < 4; j++) {
            int tok = base + slot + 64 * j;
            float4 v = *(const float4*)(inputs + (size_t)tok * 256 + n * VDIM + q * 4);
            S[(8 * q) * SSP + col + 64 * j] = pack2(v.x, v.y);
            S[(8 * q + 4) * SSP + col + 64 * j] = pack2(v.z, v.w);
        }
        __syncwarp();

        const float* Wq_t = W_s + WB_T + q * QS_WT;
        const float* Wq_p = W_s + WB_P + q * QS_BIG;
        const float* Wq_1 = W_s + WB_1 + q * QS_BIG;
        const float* Wq_2 = W_s + WB_2 + q * QS_BIG;
        const float* Wq_g = W_s + WB_G + q * QS_BIG;

        u64 acc[32];
        // t = x @ Wt + bt
        load_bias4(bias_s + 0 * DD, q, acc);
        matvec4<8>(Wq_t, Sb, acc);
        __syncwarp();
        store_stage(S, col, q, acc);      // S = t
        __syncwarp();
        // residual = t @ Wp + bp -> R
        load_bias4(bias_s + 1 * DD, q, acc);
        matvec4<32>(Wq_p, Sb, acc);
        store_stage(R, col, q, acc);
        __syncwarp();
        // a = t + cproj (RMW own rows: i*4+q)
        {
            const u64* cp = (const u64*)(cproj_s + n * DD + q * 16);
#pragma unroll
            for (int i = 0; i < 8; i++) {
                int r = (i * 4 + q) * SSP + col;
                u64 c = cp[i];
                u64 v0 = S[r], v1 = S[r + 64], v2 = S[r + 128], v3 = S[r + 192];
                ADD2(v0, v0, c); ADD2(v1, v1, c); ADD2(v2, v2, c); ADD2(v3, v3, c);
                S[r] = v0; S[r + 64] = v1; S[r + 128] = v2; S[r + 192] = v3;
            }
        }
        __syncwarp();
        // h1 = elu(a @ W1 + b1)
        load_bias4(bias_s + 2 * DD, q, acc);
        matvec4<32>(Wq_1, Sb, acc);
#pragma unroll
        for (int i = 0; i < 32; i++) {
            float e0, e1;
            unpack2(acc[i], e0, e1);
            acc[i] = pack2(eluf(e0), eluf(e1));
        }
        __syncwarp();
        store_stage(S, col, q, acc);      // S = h1
        __syncwarp();
        // h2 = h1 @ W2 + b2
        load_bias4(bias_s + 3 * DD, q, acc);
        matvec4<32>(Wq_2, Sb, acc);
        __syncwarp();
        store_stage(S, col, q, acc);      // S = h2
        __syncwarp();
        // gate logits
        load_bias4(bias_s + 4 * DD, q, acc);
        matvec4<32>(Wq_g, Sb, acc);
        // y = residual + sigmoid(gate)*h2
#pragma unroll
        for (int j = 0; j < 4; j++) {
#pragma unroll
            for (int i = 0; i < 8; i++) {
                int r = (i * 4 + q) * SSP + col + 64 * j;
                float g0, g1;
                unpack2(acc[j * 8 + i], g0, g1);
                u64 gpk = pack2(sigm(g0), sigm(g1));
                u64 y = R[r];
                FMA2(y, gpk, S[r]);
                acc[j * 8 + i] = y;
            }
        }
        // LayerNorm (4-lane butterfly) + weighted select
        const u64* g64 = (const u64*)(bias_s + 5 * DD + q * 16);
        const u64* be64 = (const u64*)(bias_s + 6 * DD + q * 16);
#pragma unroll
        for (int j = 0; j < 4; j++) {
            u64* a = acc + j * 8;
            u64 s2 = a[0];
#pragma unroll
            for (int i = 1; i < 8; i++) ADD2(s2, s2, a[i]);
            float sa, sb; unpack2(s2, sa, sb);
            float part = sa + sb;
            part += __shfl_xor_sync(0xffffffffu, part, 1);
            part += __shfl_xor_sync(0xffffffffu, part, 2);
            float mu = part * (1.f / 64.f);
            u64 negmu = dup2(-mu);
            u64 v2 = 0ull;
#pragma unroll
            for (int i = 0; i < 8; i++) {
                u64 d; ADD2(d, a[i], negmu); FMA2(v2, d, d);
            }
            float va, vb; unpack2(v2, va, vb);
            float vpart = va + vb;
            vpart += __shfl_xor_sync(0xffffffffu, vpart, 1);
            vpart += __shfl_xor_sync(0xffffffffu, vpart, 2);
            float var = vpart * (1.f / 64.f);
            u64 rs2 = dup2(rsqrtf(var + LN_EPS));
            u64 w2 = dup2(wsel_s[(slot + 64 * j) * NVARS + n]);
#pragma unroll
            for (int i = 0; i < 8; i++) {
                u64 d, t2, y;
                ADD2(d, a[i], negmu);
                MUL2(t2, d, rs2);
                y = be64[i];
                FMA2(y, t2, g64[i]);
                FMA2(sel[j * 8 + i], w2, y);
            }
        }
    }

    // output: 16 dims x 4 tokens
#pragma unroll
    for (int j = 0; j < 4; j++) {
        int tok = base + slot + 64 * j;
        ulonglong2* op = (ulonglong2*)(selected + (size_t)tok * DD + q * 16);
#pragma unroll
        for (int m = 0; m < 4; m++) {
            ulonglong2 o;
            o.x = sel[j * 8 + 2 * m];
            o.y = sel[j * 8 + 2 * m + 1];
            op[m] = o;
        }
    }
}

// ---------------------------------------------------------------------------
extern "C" void kernel_launch(void* const* d_in, const int* in_sizes, int n_in,
                              void* d_out, int out_size) {
    const float* inputs  = (const float*)d_in[0];
    const float* context = (const float*)d_in[1];
    const float* Wt   = (const float*)d_in[2];
    const float* bt   = (const float*)d_in[3];
    const float* Wctx = (const float*)d_in[4];
    const float* W1   = (const float*)d_in[5];
    const float* b1   = (const float*)d_in[6];
    const float* W2   = (const float*)d_in[7];
    const float* b2   = (const float*)d_in[8];
    const float* Wg   = (const float*)d_in[9];
    const float* bg   = (const float*)d_in[10];
    const float* Wp   = (const float*)d_in[11];
    const float* bp   = (const float*)d_in[12];
    const float* gam  = (const float*)d_in[13];
    const float* bet  = (const float*)d_in[14];
    const float* Ws   = (const float*)d_in[15];
    const float* bs   = (const float*)d_in[16];

    float* selected = (float*)d_out;
    float* wout = selected + (size_t)NTOK * DD;

    size_t smem_bytes = (size_t)SMEM_FLOATS * sizeof(float);
    cudaFuncSetAttribute(vsn_fused_kernel,
                         cudaFuncAttributeMaxDynamicSharedMemorySize,
                         (int)smem_bytes);
    vsn_fused_kernel<<<NTOK / TOKCTA, TPB, smem_bytes>>>(
        inputs, context, Wt, bt, Wctx, W1, b1, W2, b2, Wg, bg, Wp, bp,
        gam, bet, Ws, bs, selected, wout);
}